// round 2
// baseline (speedup 1.0000x reference)
#include <cuda_runtime.h>

// Problem constants (fixed by the dataset)
#define B_TOTAL   131072
#define S_DIM     17
#define A_DIM     7
#define DPHI      128
#define DPSI      8

#define TILE      256                 // samples per k_main block
#define NBLK_MAIN (B_TOTAL / TILE)    // 512 blocks

// Scratch: per-i partial C (128 x 128 floats = 64 KB), final C (136 padded),
// and a completion counter for the last-block reduction.
__device__ float        g_Cpart[DPHI * 128];
__device__ float        g_C[S_DIM * 8];      // padded [17][8]; pad stays 0
__device__ unsigned int g_count = 0;

// ---------------------------------------------------------------------------
// Kernel 1: block i computes C_i[s,a] = sum_{j,z} w[i]*K[i,j,z]*Wphi[j,s]*Wpsi[z,a]
// Last block to finish reduces all 128 partials into g_C (fixed order =>
// deterministic), then resets the counter for the next graph replay.
// ---------------------------------------------------------------------------
__global__ __launch_bounds__(256)
void k_partialC(const float* __restrict__ Wphi,   // [128,17]
                const float* __restrict__ Wpsi,   // [8,7]
                const float* __restrict__ K,      // [128,128,8]
                const float* __restrict__ wlin)   // [1,128]
{
    __shared__ float Msm[DPHI * DPSI];   // 1024 floats, layout j*8+z
    __shared__ float Ctmp[256];
    __shared__ bool  isLast;

    const int i   = blockIdx.x;          // one i per block (128 blocks)
    const int tid = threadIdx.x;         // 256 threads

    // --- M_i[j,z] = w[i] * K[i,j,z]; one float4 per thread ---
    {
        const float w = __ldg(&wlin[i]);
        const float4 kv = reinterpret_cast<const float4*>(K)[i * 256 + tid];
        float4 m;
        m.x = w * kv.x; m.y = w * kv.y; m.z = w * kv.z; m.w = w * kv.w;
        reinterpret_cast<float4*>(Msm)[tid] = m;
    }
    __syncthreads();

    // --- C partial: 2 threads per (s,a), each covering half the j range ---
    float c = 0.f;
    if (tid < 2 * S_DIM * A_DIM) {       // 238 active threads
        const int o    = tid >> 1;
        const int half = tid & 1;
        const int s = o / A_DIM;
        const int a = o - s * A_DIM;

        float psi[DPSI];
#pragma unroll
        for (int z = 0; z < DPSI; z++) psi[z] = __ldg(&Wpsi[z * A_DIM + a]);

        const int j0 = half * 64;
#pragma unroll 4
        for (int j = j0; j < j0 + 64; j++) {
            float inner = 0.f;
#pragma unroll
            for (int z = 0; z < DPSI; z++)
                inner = fmaf(Msm[j * DPSI + z], psi[z], inner);
            c = fmaf(__ldg(&Wphi[j * S_DIM + s]), inner, c);
        }
    }
    Ctmp[tid] = c;
    __syncthreads();

    if (tid < S_DIM * A_DIM)             // 119 partial outputs
        g_Cpart[i * 128 + tid] = Ctmp[2 * tid] + Ctmp[2 * tid + 1];

    // --- last-block reduction into g_C (deterministic order) ---
    __threadfence();
    if (tid == 0) {
        unsigned int done = atomicAdd(&g_count, 1u);
        isLast = (done == DPHI - 1);
    }
    __syncthreads();

    if (isLast) {
        if (tid < S_DIM * A_DIM) {
            float v = 0.f;
#pragma unroll 8
            for (int p = 0; p < DPHI; p++) v += g_Cpart[p * 128 + tid];
            const int s = tid / A_DIM;
            const int a = tid - s * A_DIM;
            g_C[s * 8 + a] = v;          // pad column 7 never written: stays 0
        }
        __syncthreads();
        if (tid == 0) g_count = 0;       // reset for next graph replay
    }
}

// ---------------------------------------------------------------------------
// Kernel 2: out[b] = state[b,:] * C * action[b,:]
// Block = 256 samples. Tiles staged via float4 coalesced loads (6 LDG.128
// per thread), compute from smem (stride 17 / 7 => conflict-free), C read
// as broadcast LDS.128.
// ---------------------------------------------------------------------------
__global__ __launch_bounds__(256)
void k_main(const float* __restrict__ state,   // [B,17]
            const float* __restrict__ action,  // [B,7]
            float* __restrict__ out)           // [B]
{
    __shared__ float Ss[TILE * S_DIM];   // 4352 floats
    __shared__ float As[TILE * A_DIM];   // 1792 floats
    __shared__ float Csm[S_DIM * 8];     // 136 floats (padded)

    const int tid = threadIdx.x;
    const int bx  = blockIdx.x;

    // stage state tile: 4352 floats = 1088 float4 (4 full rounds + 64)
    {
        const float4* S4 = reinterpret_cast<const float4*>(state) + (size_t)bx * 1088;
        float4* D = reinterpret_cast<float4*>(Ss);
#pragma unroll
        for (int k = 0; k < 4; k++) D[tid + k * 256] = S4[tid + k * 256];
        if (tid < 64) D[tid + 1024] = S4[tid + 1024];
    }
    // stage action tile: 1792 floats = 448 float4
    {
        const float4* A4 = reinterpret_cast<const float4*>(action) + (size_t)bx * 448;
        float4* D = reinterpret_cast<float4*>(As);
        D[tid] = A4[tid];
        if (tid < 192) D[tid + 256] = A4[tid + 256];
    }
    if (tid < S_DIM * 8) Csm[tid] = g_C[tid];
    __syncthreads();

    // per-thread action vector in registers
    float av0 = As[tid * A_DIM + 0];
    float av1 = As[tid * A_DIM + 1];
    float av2 = As[tid * A_DIM + 2];
    float av3 = As[tid * A_DIM + 3];
    float av4 = As[tid * A_DIM + 4];
    float av5 = As[tid * A_DIM + 5];
    float av6 = As[tid * A_DIM + 6];

    const float4* C4 = reinterpret_cast<const float4*>(Csm);
    const float*  st = Ss + tid * S_DIM;

    float r = 0.f;
#pragma unroll
    for (int s = 0; s < S_DIM; s++) {
        const float4 c0 = C4[2 * s];       // C[s][0..3]   (broadcast)
        const float4 c1 = C4[2 * s + 1];   // C[s][4..6],pad
        float t;
        t = c0.x * av0;
        t = fmaf(c0.y, av1, t);
        t = fmaf(c0.z, av2, t);
        t = fmaf(c0.w, av3, t);
        t = fmaf(c1.x, av4, t);
        t = fmaf(c1.y, av5, t);
        t = fmaf(c1.z, av6, t);
        r = fmaf(st[s], t, r);
    }

    out[bx * TILE + tid] = r;
}

// ---------------------------------------------------------------------------
extern "C" void kernel_launch(void* const* d_in, const int* in_sizes, int n_in,
                              void* d_out, int out_size)
{
    const float* state  = (const float*)d_in[0];
    const float* action = (const float*)d_in[1];
    const float* Wphi   = (const float*)d_in[2];
    const float* Wpsi   = (const float*)d_in[3];
    const float* K      = (const float*)d_in[4];
    const float* wlin   = (const float*)d_in[5];
    float* out = (float*)d_out;

    k_partialC<<<DPHI, 256>>>(Wphi, Wpsi, K, wlin);
    k_main<<<NBLK_MAIN, 256>>>(state, action, out);
}

// round 3
// speedup vs baseline: 1.0738x; 1.0738x over previous
#include <cuda_runtime.h>

// Problem constants (fixed by the dataset)
#define B_TOTAL   131072
#define S_DIM     17
#define A_DIM     7
#define DPHI      128
#define DPSI      8

#define NPART     32                  // blocks in the precompute kernel
#define I_PER     (DPHI / NPART)      // 4 i-values per block

#define TILE      512                 // samples per k_main block
#define NBLK_MAIN (B_TOTAL / TILE)    // 256 blocks

// Per-block partial C matrices (32 x 128 floats = 16 KB); reduced in k_main.
__device__ float g_Cpart[NPART * 128];

// ---------------------------------------------------------------------------
// Kernel 1: block p computes partial C over i in [p*I_PER, (p+1)*I_PER).
//   M_p[j,z] = sum_{i in chunk} w_lin[i] * K[i,j,z]
//   C_p[s,a] = sum_{j,z} M_p[j,z] * W_phi[j,s] * W_psi[z,a]
// 512 threads: 4 threads per (s,a), each covering 32 j-values.
// ---------------------------------------------------------------------------
__global__ __launch_bounds__(512)
void k_partialC(const float* __restrict__ Wphi,   // [128,17]
                const float* __restrict__ Wpsi,   // [8,7]
                const float* __restrict__ K,      // [128,128,8]
                const float* __restrict__ wlin)   // [1,128]
{
    __shared__ float Msm[DPHI * DPSI];   // 1024 floats, layout j*8+z
    __shared__ float Ctmp[512];

    const int p   = blockIdx.x;
    const int tid = threadIdx.x;         // 512 threads

    // --- M partial: threads 0..255 each own one float4 of the 1024 floats ---
    if (tid < 256) {
        const float4* K4 = reinterpret_cast<const float4*>(K);
        float4 acc = make_float4(0.f, 0.f, 0.f, 0.f);
#pragma unroll
        for (int ii = 0; ii < I_PER; ii++) {
            const int i = p * I_PER + ii;
            const float w = __ldg(&wlin[i]);
            const float4 kv = K4[i * 256 + tid];
            acc.x = fmaf(w, kv.x, acc.x);
            acc.y = fmaf(w, kv.y, acc.y);
            acc.z = fmaf(w, kv.z, acc.z);
            acc.w = fmaf(w, kv.w, acc.w);
        }
        reinterpret_cast<float4*>(Msm)[tid] = acc;
    }
    __syncthreads();

    // --- C partial: 4 threads per (s,a), each covering 32 j-values ---
    float c = 0.f;
    if (tid < 4 * S_DIM * A_DIM) {       // 476 active threads
        const int o = tid >> 2;
        const int q = tid & 3;
        const int s = o / A_DIM;
        const int a = o - s * A_DIM;

        float psi[DPSI];
#pragma unroll
        for (int z = 0; z < DPSI; z++) psi[z] = __ldg(&Wpsi[z * A_DIM + a]);

        const int j0 = q * 32;
#pragma unroll 4
        for (int j = j0; j < j0 + 32; j++) {
            float inner = 0.f;
#pragma unroll
            for (int z = 0; z < DPSI; z++)
                inner = fmaf(Msm[j * DPSI + z], psi[z], inner);
            c = fmaf(__ldg(&Wphi[j * S_DIM + s]), inner, c);
        }
    }
    Ctmp[tid] = c;
    __syncthreads();

    if (tid < S_DIM * A_DIM)             // 119 partial outputs
        g_Cpart[p * 128 + tid] = (Ctmp[4 * tid] + Ctmp[4 * tid + 1])
                               + (Ctmp[4 * tid + 2] + Ctmp[4 * tid + 3]);
}

// ---------------------------------------------------------------------------
// Kernel 2: out[b] = state[b,:] * C * action[b,:]
// Block = 512 samples, 256 threads (2 samples/thread). 12 float4 staging
// loads per thread issued before the first sync (high MLP). Partial-C
// reduction accumulated in registers concurrently, then parked in the As
// smem region (aliased) after action values are pulled to registers.
// Static smem = 34816 + 14336 = 49152 B (exactly the 48 KB static limit).
// ---------------------------------------------------------------------------
__global__ __launch_bounds__(256)
void k_main(const float* __restrict__ state,   // [B,17]
            const float* __restrict__ action,  // [B,7]
            float* __restrict__ out)           // [B]
{
    __shared__ __align__(16) float Ss[TILE * S_DIM];   // 34816 B
    __shared__ __align__(16) float As[TILE * A_DIM];   // 14336 B; first 136
                                                       // floats reused as C
    const int tid = threadIdx.x;
    const int bx  = blockIdx.x;

    // --- partial-C reduction into a register (independent of staging) ---
    // tid < 136 maps to padded [17][8]; col 7 is the zero pad.
    float credv = 0.f;
    if (tid < S_DIM * 8) {
        const int row = tid >> 3;
        const int col = tid & 7;
        if (col < A_DIM) {
            const int q = row * A_DIM + col;
#pragma unroll 8
            for (int pp = 0; pp < NPART; pp++)
                credv += g_Cpart[pp * 128 + q];
        }
    }

    // --- stage state tile: 2176 float4 = 8 full rounds + 128 ---
    {
        const float4* S4 = reinterpret_cast<const float4*>(state) + (size_t)bx * 2176;
        float4* D = reinterpret_cast<float4*>(Ss);
#pragma unroll
        for (int k = 0; k < 8; k++) D[tid + k * 256] = S4[tid + k * 256];
        if (tid < 128) D[tid + 2048] = S4[tid + 2048];
    }
    // --- stage action tile: 896 float4 = 3 full rounds + 128 ---
    {
        const float4* A4 = reinterpret_cast<const float4*>(action) + (size_t)bx * 896;
        float4* D = reinterpret_cast<float4*>(As);
#pragma unroll
        for (int k = 0; k < 3; k++) D[tid + k * 256] = A4[tid + k * 256];
        if (tid < 128) D[tid + 768] = A4[tid + 768];
    }
    __syncthreads();

    // --- pull both samples' action vectors to registers ---
    const float* aA = As + tid * A_DIM;
    const float* aB = As + (tid + 256) * A_DIM;
    float avA0 = aA[0], avA1 = aA[1], avA2 = aA[2], avA3 = aA[3];
    float avA4 = aA[4], avA5 = aA[5], avA6 = aA[6];
    float avB0 = aB[0], avB1 = aB[1], avB2 = aB[2], avB3 = aB[3];
    float avB4 = aB[4], avB5 = aB[5], avB6 = aB[6];
    __syncthreads();

    // --- park reduced C (padded [17][8]) in the As region ---
    if (tid < S_DIM * 8) As[tid] = credv;   // pad column written as 0
    __syncthreads();

    const float4* C4  = reinterpret_cast<const float4*>(As);
    const float*  stA = Ss + tid * S_DIM;
    const float*  stB = Ss + (tid + 256) * S_DIM;

    float rA = 0.f, rB = 0.f;
#pragma unroll
    for (int s = 0; s < S_DIM; s++) {
        const float4 c0 = C4[2 * s];       // C[s][0..3] (warp broadcast)
        const float4 c1 = C4[2 * s + 1];   // C[s][4..6], pad
        float tA, tB;
        tA = c0.x * avA0;                 tB = c0.x * avB0;
        tA = fmaf(c0.y, avA1, tA);        tB = fmaf(c0.y, avB1, tB);
        tA = fmaf(c0.z, avA2, tA);        tB = fmaf(c0.z, avB2, tB);
        tA = fmaf(c0.w, avA3, tA);        tB = fmaf(c0.w, avB3, tB);
        tA = fmaf(c1.x, avA4, tA);        tB = fmaf(c1.x, avB4, tB);
        tA = fmaf(c1.y, avA5, tA);        tB = fmaf(c1.y, avB5, tB);
        tA = fmaf(c1.z, avA6, tA);        tB = fmaf(c1.z, avB6, tB);
        rA = fmaf(stA[s], tA, rA);        rB = fmaf(stB[s], tB, rB);
    }

    out[bx * TILE + tid]       = rA;
    out[bx * TILE + tid + 256] = rB;
}

// ---------------------------------------------------------------------------
extern "C" void kernel_launch(void* const* d_in, const int* in_sizes, int n_in,
                              void* d_out, int out_size)
{
    const float* state  = (const float*)d_in[0];
    const float* action = (const float*)d_in[1];
    const float* Wphi   = (const float*)d_in[2];
    const float* Wpsi   = (const float*)d_in[3];
    const float* K      = (const float*)d_in[4];
    const float* wlin   = (const float*)d_in[5];
    float* out = (float*)d_out;

    k_partialC<<<NPART, 512>>>(Wphi, Wpsi, K, wlin);
    k_main<<<NBLK_MAIN, 256>>>(state, action, out);
}